// round 1
// baseline (speedup 1.0000x reference)
#include <cuda_runtime.h>
#include <cstddef>

// Problem constants (fixed by the dataset)
#define TT 128
#define BB 64
#define EE 1024
#define HH 1024
#define VV 10000
#define LL 2

#define MREST (127 * 64)   // 8128 rows for t = 1..127

// ---------------- scratch (device globals; no allocations allowed) ----------
__device__ float g_bufA[MREST * 1024];
__device__ float g_bufB[MREST * 1024];
__device__ float g_x0 [BB * EE];
__device__ float g_xt [BB * EE];
__device__ float g_xt2[BB * EE];
__device__ float g_h00[BB * HH];
__device__ float g_h01[BB * HH];
__device__ float g_aU0[BB * HH];
__device__ float g_aU1[BB * HH];

// ---------------- embedding gather ------------------------------------------
// X[r, :] = emb_table[inputs[r + ioff], :]   (1024 floats per row, float4 copy)
__global__ void gather_emb(const int* __restrict__ inputs,
                           const float* __restrict__ emb,
                           float* __restrict__ X,
                           int ioff, int nrows)
{
    int idx = blockIdx.x * blockDim.x + threadIdx.x;
    int total = nrows * 256;                // 256 float4 per row
    if (idx >= total) return;
    int r = idx >> 8;
    int c = idx & 255;
    int tok = inputs[r + ioff];
    reinterpret_cast<float4*>(X)[(size_t)r * 256 + c] =
        reinterpret_cast<const float4*>(emb)[(size_t)tok * 256 + c];
}

// ---------------- SGEMM: C = A(MxK) * W(NxK)^T + bias, fused epilogues ------
// EPI 0: C[m,n] = acc + bias[n]                        (scratch)
// EPI 1: C[m,n] = tanh(acc + bias[n])                  (scratch)
// EPI 2: v = tanh(acc + bias[n] + aU[(m%64),n]); C=v; also store to h_all:
//        O[(((t0 + m/64)*L + l)*64 + (m%64))*1024 + n] = v   (N must be 1024)
// EPI 3: O[(m + row_off)*N + n] = acc + bias[n]        (logits, direct)
#define BM 128
#define BN 128
#define BK 8
#define SMPAD 132   // padded stride for shared tiles (conflict-free stores)

template <int EPI>
__global__ __launch_bounds__(256)
void sgemm_nt(int M, int N, int K,
              const float* __restrict__ A,
              const float* __restrict__ W,
              const float* __restrict__ bias,
              const float* __restrict__ aU,
              float* __restrict__ C,
              float* __restrict__ O,
              int t0, int l, int row_off)
{
    __shared__ float As[BK][SMPAD];
    __shared__ float Ws[BK][SMPAD];

    const int tid = threadIdx.x;
    const int bm = blockIdx.y * BM;
    const int bn = blockIdx.x * BN;

    const int tx = tid & 15;    // N direction
    const int ty = tid >> 4;    // M direction

    // loader mapping: each thread loads one float4 of A and one of W
    const int ldr = tid >> 1;            // 0..127: tile row
    const int ldc = (tid & 1) * 4;       // 0 or 4: k offset

    float acc[8][8];
#pragma unroll
    for (int i = 0; i < 8; i++)
#pragma unroll
        for (int j = 0; j < 8; j++) acc[i][j] = 0.0f;

    for (int k0 = 0; k0 < K; k0 += BK) {
        // load A tile (transposed into As[k][m])
        {
            int gm = bm + ldr;
            float4 v = make_float4(0.f, 0.f, 0.f, 0.f);
            if (gm < M)
                v = *reinterpret_cast<const float4*>(&A[(size_t)gm * K + k0 + ldc]);
            As[ldc + 0][ldr] = v.x;
            As[ldc + 1][ldr] = v.y;
            As[ldc + 2][ldr] = v.z;
            As[ldc + 3][ldr] = v.w;
        }
        // load W tile (transposed into Ws[k][n])
        {
            int gn = bn + ldr;
            float4 v = make_float4(0.f, 0.f, 0.f, 0.f);
            if (gn < N)
                v = *reinterpret_cast<const float4*>(&W[(size_t)gn * K + k0 + ldc]);
            Ws[ldc + 0][ldr] = v.x;
            Ws[ldc + 1][ldr] = v.y;
            Ws[ldc + 2][ldr] = v.z;
            Ws[ldc + 3][ldr] = v.w;
        }
        __syncthreads();

#pragma unroll
        for (int k = 0; k < BK; k++) {
            float a[8], b[8];
            float4 a0 = *reinterpret_cast<const float4*>(&As[k][ty * 8]);
            float4 a1 = *reinterpret_cast<const float4*>(&As[k][ty * 8 + 4]);
            float4 b0 = *reinterpret_cast<const float4*>(&Ws[k][tx * 8]);
            float4 b1 = *reinterpret_cast<const float4*>(&Ws[k][tx * 8 + 4]);
            a[0]=a0.x; a[1]=a0.y; a[2]=a0.z; a[3]=a0.w;
            a[4]=a1.x; a[5]=a1.y; a[6]=a1.z; a[7]=a1.w;
            b[0]=b0.x; b[1]=b0.y; b[2]=b0.z; b[3]=b0.w;
            b[4]=b1.x; b[5]=b1.y; b[6]=b1.z; b[7]=b1.w;
#pragma unroll
            for (int i = 0; i < 8; i++)
#pragma unroll
                for (int j = 0; j < 8; j++)
                    acc[i][j] = fmaf(a[i], b[j], acc[i][j]);
        }
        __syncthreads();
    }

    // epilogue
#pragma unroll
    for (int i = 0; i < 8; i++) {
        int gm = bm + ty * 8 + i;
        if (gm >= M) continue;
#pragma unroll
        for (int j = 0; j < 8; j++) {
            int gn = bn + tx * 8 + j;
            if (gn >= N) continue;
            float v = acc[i][j] + bias[gn];
            if (EPI == 0) {
                C[(size_t)gm * N + gn] = v;
            } else if (EPI == 1) {
                C[(size_t)gm * N + gn] = tanhf(v);
            } else if (EPI == 2) {
                v += aU[(size_t)(gm & 63) * N + gn];
                v = tanhf(v);
                C[(size_t)gm * N + gn] = v;
                int t = t0 + (gm >> 6);
                int b = gm & 63;
                O[(((size_t)t * LL + l) * BB + b) * HH + gn] = v;
            } else { // EPI == 3
                O[(size_t)(gm + row_off) * N + gn] = v;
            }
        }
    }
}

// ---------------- host-side orchestration -----------------------------------
static inline dim3 gemm_grid(int M, int N) {
    return dim3((N + BN - 1) / BN, (M + BM - 1) / BM);
}

extern "C" void kernel_launch(void* const* d_in, const int* in_sizes, int n_in,
                              void* d_out, int out_size)
{
    (void)in_sizes; (void)n_in; (void)out_size;
    const int*   inputs = (const int*)  d_in[0];
    const float* hidden = (const float*)d_in[1];   // (L,B,H)
    const float* emb    = (const float*)d_in[2];   // (V,E)
    const float* Ww     = (const float*)d_in[3];   // (L,H,E)
    const float* Wb     = (const float*)d_in[4];   // (L,H)
    const float* Uw     = (const float*)d_in[5];   // (L,H,H)
    const float* Ub     = (const float*)d_in[6];   // (L,H)
    const float* Fw     = (const float*)d_in[7];   // (L,E,H)
    const float* Fb     = (const float*)d_in[8];   // (L,E)
    const float* Dw     = (const float*)d_in[9];   // (V,H)
    const float* Db     = (const float*)d_in[10];  // (V,)

    float* out  = (float*)d_out;
    float* hall = out + (size_t)TT * BB * VV;      // h_all after logits

    float *bufA, *bufB, *x0, *xt, *xt2, *h00, *h01, *aU0, *aU1;
    cudaGetSymbolAddress((void**)&bufA, g_bufA);
    cudaGetSymbolAddress((void**)&bufB, g_bufB);
    cudaGetSymbolAddress((void**)&x0,  g_x0);
    cudaGetSymbolAddress((void**)&xt,  g_xt);
    cudaGetSymbolAddress((void**)&xt2, g_xt2);
    cudaGetSymbolAddress((void**)&h00, g_h00);
    cudaGetSymbolAddress((void**)&h01, g_h01);
    cudaGetSymbolAddress((void**)&aU0, g_aU0);
    cudaGetSymbolAddress((void**)&aU1, g_aU1);

    const size_t Wstride = (size_t)HH * EE;   // per-layer stride (all 1024*1024)

    // ---- Phase A: t = 0 (sequential small GEMMs, M = 64) ----
    gather_emb<<<(BB * 256 + 255) / 256, 256>>>(inputs, emb, x0, 0, BB);

    // aU0p = hidden[0] @ Uw0^T + Ub0
    sgemm_nt<0><<<gemm_grid(BB, HH), 256>>>(BB, HH, HH, hidden, Uw, Ub,
                                            nullptr, aU0, nullptr, 0, 0, 0);
    // h00 = tanh(x0 @ Ww0^T + Wb0 + aU0p) -> scratch + h_all(t=0, l=0)
    sgemm_nt<2><<<gemm_grid(BB, HH), 256>>>(BB, HH, EE, x0, Ww, Wb,
                                            aU0, h00, hall, 0, 0, 0);
    // xt = tanh(h00 @ Fw0^T + Fb0)
    sgemm_nt<1><<<gemm_grid(BB, EE), 256>>>(BB, EE, HH, h00, Fw, Fb,
                                            nullptr, xt, nullptr, 0, 0, 0);
    // aU1p = hidden[1] @ Uw1^T + Ub1
    sgemm_nt<0><<<gemm_grid(BB, HH), 256>>>(BB, HH, HH, hidden + (size_t)BB * HH,
                                            Uw + Wstride, Ub + HH,
                                            nullptr, aU1, nullptr, 0, 0, 0);
    // h01 = tanh(xt @ Ww1^T + Wb1 + aU1p) -> scratch + h_all(t=0, l=1)
    sgemm_nt<2><<<gemm_grid(BB, HH), 256>>>(BB, HH, EE, xt, Ww + Wstride, Wb + HH,
                                            aU1, h01, hall, 0, 1, 0);
    // xt2 = tanh(h01 @ Fw1^T + Fb1)
    sgemm_nt<1><<<gemm_grid(BB, EE), 256>>>(BB, EE, HH, h01, Fw + Wstride, Fb + EE,
                                            nullptr, xt2, nullptr, 0, 0, 0);
    // logits[0] = xt2 @ Dw^T + Db   (rows 0..63 of out)
    sgemm_nt<3><<<gemm_grid(BB, VV), 256>>>(BB, VV, HH, xt2, Dw, Db,
                                            nullptr, nullptr, out, 0, 0, 0);

    // ---- fixed recurrent terms for t >= 1 ----
    sgemm_nt<0><<<gemm_grid(BB, HH), 256>>>(BB, HH, HH, h00, Uw, Ub,
                                            nullptr, aU0, nullptr, 0, 0, 0);
    sgemm_nt<0><<<gemm_grid(BB, HH), 256>>>(BB, HH, HH, h01, Uw + Wstride, Ub + HH,
                                            nullptr, aU1, nullptr, 0, 0, 0);

    // ---- Phase B: t = 1..127 batched (M = 8128) ----
    gather_emb<<<(MREST * 256 + 255) / 256, 256>>>(inputs, emb, bufA, BB, MREST);

    // H1 = tanh(X @ Ww0^T + Wb0 + aU0[b]) -> bufB + h_all(t0=1, l=0)
    sgemm_nt<2><<<gemm_grid(MREST, HH), 256>>>(MREST, HH, EE, bufA, Ww, Wb,
                                               aU0, bufB, hall, 1, 0, 0);
    // X1 = tanh(H1 @ Fw0^T + Fb0) -> bufA
    sgemm_nt<1><<<gemm_grid(MREST, EE), 256>>>(MREST, EE, HH, bufB, Fw, Fb,
                                               nullptr, bufA, nullptr, 0, 0, 0);
    // H2 = tanh(X1 @ Ww1^T + Wb1 + aU1[b]) -> bufB + h_all(t0=1, l=1)
    sgemm_nt<2><<<gemm_grid(MREST, HH), 256>>>(MREST, HH, EE, bufA,
                                               Ww + Wstride, Wb + HH,
                                               aU1, bufB, hall, 1, 1, 0);
    // X2 = tanh(H2 @ Fw1^T + Fb1) -> bufA
    sgemm_nt<1><<<gemm_grid(MREST, EE), 256>>>(MREST, EE, HH, bufB,
                                               Fw + Wstride, Fb + EE,
                                               nullptr, bufA, nullptr, 0, 0, 0);
    // logits[1:] = X2 @ Dw^T + Db   (rows 64.. of out)
    sgemm_nt<3><<<gemm_grid(MREST, VV), 256>>>(MREST, VV, HH, bufA, Dw, Db,
                                               nullptr, nullptr, out, 0, 0, BB);
}

// round 2
// speedup vs baseline: 1.2118x; 1.2118x over previous
#include <cuda_runtime.h>
#include <cstddef>

// Problem constants (fixed by the dataset)
#define TT 128
#define BB 64
#define EE 1024
#define HH 1024
#define VV 10000
#define LL 2

#define MREST (127 * 64)   // 8128 rows for t = 1..127

// ---------------- scratch (device globals; no allocations allowed) ----------
__device__ float g_bufA[MREST * 1024];
__device__ float g_bufB[MREST * 1024];
__device__ float g_x0 [BB * EE];
__device__ float g_xt [BB * EE];
__device__ float g_xt2[BB * EE];
__device__ float g_h00[BB * HH];
__device__ float g_h01[BB * HH];
__device__ float g_aU0[BB * HH];
__device__ float g_aU1[BB * HH];
__device__ float g_part[4 * 64 * 10016];   // split-K partials (max: nsplit=4, N=10000)

// ---------------- embedding gather ------------------------------------------
__global__ void gather_emb(const int* __restrict__ inputs,
                           const float* __restrict__ emb,
                           float* __restrict__ X,
                           int ioff, int nrows)
{
    int idx = blockIdx.x * blockDim.x + threadIdx.x;
    int total = nrows * 256;                // 256 float4 per row
    if (idx >= total) return;
    int r = idx >> 8;
    int c = idx & 255;
    int tok = inputs[r + ioff];
    reinterpret_cast<float4*>(X)[(size_t)r * 256 + c] =
        reinterpret_cast<const float4*>(emb)[(size_t)tok * 256 + c];
}

// =======================================================================
// Small-M (M=64) split-K GEMM: partial[s][m][n] = sum_{k in chunk s} A[m,k]*W[n,k]
// grid = (ceil(N/64), nsplit), 256 threads, 4x4 microtile
// =======================================================================
__global__ __launch_bounds__(256)
void sgemm_splitk(int N, int K,
                  const float* __restrict__ A,
                  const float* __restrict__ W,
                  float* __restrict__ partial)
{
    __shared__ float As[8][68];
    __shared__ float Ws[8][68];

    const int tid = threadIdx.x;
    const int bn  = blockIdx.x * 64;
    const int s   = blockIdx.y;
    const int kc  = K / gridDim.y;    // chunk length (multiple of 8)
    const int k0  = s * kc;

    const int tx = tid & 15;          // n/4
    const int ty = tid >> 4;          // m/4

    const int lr = tid >> 2;          // 0..63 (row within tile)
    const int lk = (tid & 3) * 2;     // 0,2,4,6 (k offset)

    float acc[4][4];
#pragma unroll
    for (int i = 0; i < 4; i++)
#pragma unroll
        for (int j = 0; j < 4; j++) acc[i][j] = 0.0f;

    const int gn = bn + lr;
    const bool okW = gn < N;

    for (int kk = 0; kk < kc; kk += 8) {
        float2 av = *reinterpret_cast<const float2*>(&A[(size_t)lr * K + k0 + kk + lk]);
        float2 wv = make_float2(0.f, 0.f);
        if (okW)
            wv = *reinterpret_cast<const float2*>(&W[(size_t)gn * K + k0 + kk + lk]);
        As[lk][lr] = av.x;  As[lk + 1][lr] = av.y;
        Ws[lk][lr] = wv.x;  Ws[lk + 1][lr] = wv.y;
        __syncthreads();

#pragma unroll
        for (int k = 0; k < 8; k++) {
            float a[4], b[4];
#pragma unroll
            for (int i = 0; i < 4; i++) a[i] = As[k][ty * 4 + i];
#pragma unroll
            for (int j = 0; j < 4; j++) b[j] = Ws[k][tx * 4 + j];
#pragma unroll
            for (int i = 0; i < 4; i++)
#pragma unroll
                for (int j = 0; j < 4; j++)
                    acc[i][j] = fmaf(a[i], b[j], acc[i][j]);
        }
        __syncthreads();
    }

#pragma unroll
    for (int i = 0; i < 4; i++) {
        int m = ty * 4 + i;
#pragma unroll
        for (int j = 0; j < 4; j++) {
            int n = bn + tx * 4 + j;
            if (n < N)
                partial[((size_t)s * 64 + m) * N + n] = acc[i][j];
        }
    }
}

// split-K reduce + fused epilogue (EPI semantics match sgemm_nt)
template <int EPI>
__global__ void splitk_epi(int N, int nsplit,
                           const float* __restrict__ partial,
                           const float* __restrict__ bias,
                           const float* __restrict__ aU,
                           float* __restrict__ C,
                           float* __restrict__ O,
                           int l, int row_off)
{
    int idx = blockIdx.x * blockDim.x + threadIdx.x;
    if (idx >= 64 * N) return;
    int m = idx / N;
    int n = idx - m * N;
    float acc = 0.0f;
    for (int s = 0; s < nsplit; s++)
        acc += partial[((size_t)s * 64 + m) * N + n];
    float v = acc + bias[n];
    if (EPI == 0) {
        C[(size_t)m * N + n] = v;
    } else if (EPI == 1) {
        C[(size_t)m * N + n] = tanhf(v);
    } else if (EPI == 2) {
        v += aU[(size_t)m * N + n];
        v = tanhf(v);
        C[(size_t)m * N + n] = v;
        // t = 0 for phase A
        O[(((size_t)0 * LL + l) * BB + m) * HH + n] = v;
    } else { // EPI == 3
        O[(size_t)(m + row_off) * N + n] = v;
    }
}

// =======================================================================
// Big SGEMM: C = A(MxK) * W(NxK)^T + bias, fused epilogues, reg-prefetch DB
// =======================================================================
#define BM 128
#define BN 128
#define BK 8
#define SMPAD 132

template <int EPI>
__global__ __launch_bounds__(256)
void sgemm_nt(int M, int N, int K,
              const float* __restrict__ A,
              const float* __restrict__ W,
              const float* __restrict__ bias,
              const float* __restrict__ aU,
              float* __restrict__ C,
              float* __restrict__ O,
              int t0, int l, int row_off)
{
    __shared__ float As[BK][SMPAD];
    __shared__ float Ws[BK][SMPAD];

    const int tid = threadIdx.x;
    const int bm = blockIdx.y * BM;
    const int bn = blockIdx.x * BN;

    const int tx = tid & 15;    // N direction
    const int ty = tid >> 4;    // M direction

    const int ldr = tid >> 1;            // 0..127: tile row
    const int ldc = (tid & 1) * 4;       // 0 or 4: k offset

    float acc[8][8];
#pragma unroll
    for (int i = 0; i < 8; i++)
#pragma unroll
        for (int j = 0; j < 8; j++) acc[i][j] = 0.0f;

    const int gmA = bm + ldr;
    const int gnW = bn + ldr;
    const bool okA = gmA < M;
    const bool okW = gnW < N;
    const float* Aptr = A + (size_t)(okA ? gmA : 0) * K + ldc;
    const float* Wptr = W + (size_t)(okW ? gnW : 0) * K + ldc;
    const float4 z4 = make_float4(0.f, 0.f, 0.f, 0.f);

    float4 va = okA ? *reinterpret_cast<const float4*>(Aptr) : z4;
    float4 vw = okW ? *reinterpret_cast<const float4*>(Wptr) : z4;

    for (int k0 = 0; k0 < K; k0 += BK) {
        As[ldc + 0][ldr] = va.x;
        As[ldc + 1][ldr] = va.y;
        As[ldc + 2][ldr] = va.z;
        As[ldc + 3][ldr] = va.w;
        Ws[ldc + 0][ldr] = vw.x;
        Ws[ldc + 1][ldr] = vw.y;
        Ws[ldc + 2][ldr] = vw.z;
        Ws[ldc + 3][ldr] = vw.w;
        __syncthreads();

        if (k0 + BK < K) {   // prefetch next tile into registers
            va = okA ? *reinterpret_cast<const float4*>(Aptr + k0 + BK) : z4;
            vw = okW ? *reinterpret_cast<const float4*>(Wptr + k0 + BK) : z4;
        }

#pragma unroll
        for (int k = 0; k < BK; k++) {
            float a[8], b[8];
            float4 a0 = *reinterpret_cast<const float4*>(&As[k][ty * 8]);
            float4 a1 = *reinterpret_cast<const float4*>(&As[k][ty * 8 + 4]);
            float4 b0 = *reinterpret_cast<const float4*>(&Ws[k][tx * 8]);
            float4 b1 = *reinterpret_cast<const float4*>(&Ws[k][tx * 8 + 4]);
            a[0]=a0.x; a[1]=a0.y; a[2]=a0.z; a[3]=a0.w;
            a[4]=a1.x; a[5]=a1.y; a[6]=a1.z; a[7]=a1.w;
            b[0]=b0.x; b[1]=b0.y; b[2]=b0.z; b[3]=b0.w;
            b[4]=b1.x; b[5]=b1.y; b[6]=b1.z; b[7]=b1.w;
#pragma unroll
            for (int i = 0; i < 8; i++)
#pragma unroll
                for (int j = 0; j < 8; j++)
                    acc[i][j] = fmaf(a[i], b[j], acc[i][j]);
        }
        __syncthreads();
    }

#pragma unroll
    for (int i = 0; i < 8; i++) {
        int gm = bm + ty * 8 + i;
        if (gm >= M) continue;
#pragma unroll
        for (int j = 0; j < 8; j++) {
            int gn = bn + tx * 8 + j;
            if (gn >= N) continue;
            float v = acc[i][j] + bias[gn];
            if (EPI == 0) {
                C[(size_t)gm * N + gn] = v;
            } else if (EPI == 1) {
                C[(size_t)gm * N + gn] = tanhf(v);
            } else if (EPI == 2) {
                v += aU[(size_t)(gm & 63) * N + gn];
                v = tanhf(v);
                C[(size_t)gm * N + gn] = v;
                int t = t0 + (gm >> 6);
                int b = gm & 63;
                O[(((size_t)t * LL + l) * BB + b) * HH + gn] = v;
            } else { // EPI == 3
                O[(size_t)(gm + row_off) * N + gn] = v;
            }
        }
    }
}

// ---------------- host-side orchestration -----------------------------------
static inline dim3 gemm_grid(int M, int N) {
    return dim3((N + BN - 1) / BN, (M + BM - 1) / BM);
}

// small GEMM (M=64): splitK mainloop + reduce/epilogue
template <int EPI>
static void small_gemm(int N, int K, int nsplit,
                       const float* A, const float* W, const float* bias,
                       const float* aU, float* C, float* O,
                       int l, int row_off, float* part)
{
    dim3 g((N + 63) / 64, nsplit);
    sgemm_splitk<<<g, 256>>>(N, K, A, W, part);
    int total = 64 * N;
    splitk_epi<EPI><<<(total + 255) / 256, 256>>>(N, nsplit, part, bias, aU, C, O, l, row_off);
}

extern "C" void kernel_launch(void* const* d_in, const int* in_sizes, int n_in,
                              void* d_out, int out_size)
{
    (void)in_sizes; (void)n_in; (void)out_size;
    const int*   inputs = (const int*)  d_in[0];
    const float* hidden = (const float*)d_in[1];   // (L,B,H)
    const float* emb    = (const float*)d_in[2];   // (V,E)
    const float* Ww     = (const float*)d_in[3];   // (L,H,E)
    const float* Wb     = (const float*)d_in[4];   // (L,H)
    const float* Uw     = (const float*)d_in[5];   // (L,H,H)
    const float* Ub     = (const float*)d_in[6];   // (L,H)
    const float* Fw     = (const float*)d_in[7];   // (L,E,H)
    const float* Fb     = (const float*)d_in[8];   // (L,E)
    const float* Dw     = (const float*)d_in[9];   // (V,H)
    const float* Db     = (const float*)d_in[10];  // (V,)

    float* out  = (float*)d_out;
    float* hall = out + (size_t)TT * BB * VV;      // h_all after logits

    float *bufA, *bufB, *x0, *xt, *xt2, *h00, *h01, *aU0, *aU1, *part;
    cudaGetSymbolAddress((void**)&bufA, g_bufA);
    cudaGetSymbolAddress((void**)&bufB, g_bufB);
    cudaGetSymbolAddress((void**)&x0,  g_x0);
    cudaGetSymbolAddress((void**)&xt,  g_xt);
    cudaGetSymbolAddress((void**)&xt2, g_xt2);
    cudaGetSymbolAddress((void**)&h00, g_h00);
    cudaGetSymbolAddress((void**)&h01, g_h01);
    cudaGetSymbolAddress((void**)&aU0, g_aU0);
    cudaGetSymbolAddress((void**)&aU1, g_aU1);
    cudaGetSymbolAddress((void**)&part, g_part);

    const size_t Wstride = (size_t)HH * EE;

    // ---- Phase A: t = 0 (sequential small GEMMs, M = 64, split-K) ----
    gather_emb<<<(BB * 256 + 255) / 256, 256>>>(inputs, emb, x0, 0, BB);

    // aU0p = hidden[0] @ Uw0^T + Ub0
    small_gemm<0>(HH, HH, 16, hidden, Uw, Ub, nullptr, aU0, nullptr, 0, 0, part);
    // h00 = tanh(x0 @ Ww0^T + Wb0 + aU0p) -> scratch + h_all(t=0, l=0)
    small_gemm<2>(HH, EE, 16, x0, Ww, Wb, aU0, h00, hall, 0, 0, part);
    // xt = tanh(h00 @ Fw0^T + Fb0)
    small_gemm<1>(EE, HH, 16, h00, Fw, Fb, nullptr, xt, nullptr, 0, 0, part);
    // aU1p = hidden[1] @ Uw1^T + Ub1
    small_gemm<0>(HH, HH, 16, hidden + (size_t)BB * HH, Uw + Wstride, Ub + HH,
                  nullptr, aU1, nullptr, 0, 0, part);
    // h01 = tanh(xt @ Ww1^T + Wb1 + aU1p) -> scratch + h_all(t=0, l=1)
    small_gemm<2>(HH, EE, 16, xt, Ww + Wstride, Wb + HH, aU1, h01, hall, 1, 0, part);
    // xt2 = tanh(h01 @ Fw1^T + Fb1)
    small_gemm<1>(EE, HH, 16, h01, Fw + Wstride, Fb + EE, nullptr, xt2, nullptr, 0, 0, part);
    // logits[0] = xt2 @ Dw^T + Db   (rows 0..63 of out)
    small_gemm<3>(VV, HH, 4, xt2, Dw, Db, nullptr, nullptr, out, 0, 0, part);

    // ---- fixed recurrent terms for t >= 1 ----
    small_gemm<0>(HH, HH, 16, h00, Uw, Ub, nullptr, aU0, nullptr, 0, 0, part);
    small_gemm<0>(HH, HH, 16, h01, Uw + Wstride, Ub + HH, nullptr, aU1, nullptr, 0, 0, part);

    // ---- Phase B: t = 1..127 batched (M = 8128) ----
    gather_emb<<<(MREST * 256 + 255) / 256, 256>>>(inputs, emb, bufA, BB, MREST);

    // H1 = tanh(X @ Ww0^T + Wb0 + aU0[b]) -> bufB + h_all(t0=1, l=0)
    sgemm_nt<2><<<gemm_grid(MREST, HH), 256>>>(MREST, HH, EE, bufA, Ww, Wb,
                                               aU0, bufB, hall, 1, 0, 0);
    // X1 = tanh(H1 @ Fw0^T + Fb0) -> bufA
    sgemm_nt<1><<<gemm_grid(MREST, EE), 256>>>(MREST, EE, HH, bufB, Fw, Fb,
                                               nullptr, bufA, nullptr, 0, 0, 0);
    // H2 = tanh(X1 @ Ww1^T + Wb1 + aU1[b]) -> bufB + h_all(t0=1, l=1)
    sgemm_nt<2><<<gemm_grid(MREST, HH), 256>>>(MREST, HH, EE, bufA,
                                               Ww + Wstride, Wb + HH,
                                               aU1, bufB, hall, 1, 1, 0);
    // X2 = tanh(H2 @ Fw1^T + Fb1) -> bufA
    sgemm_nt<1><<<gemm_grid(MREST, EE), 256>>>(MREST, EE, HH, bufB,
                                               Fw + Wstride, Fb + EE,
                                               nullptr, bufA, nullptr, 0, 0, 0);
    // logits[1:] = X2 @ Dw^T + Db   (rows 64.. of out)
    sgemm_nt<3><<<gemm_grid(MREST, VV), 256>>>(MREST, VV, HH, bufA, Dw, Db,
                                               nullptr, nullptr, out, 0, 0, BB);
}

// round 3
// speedup vs baseline: 2.7918x; 2.3038x over previous
#include <cuda_runtime.h>
#include <cstddef>

// Problem constants (fixed by the dataset)
#define TT 128
#define BB 64
#define EE 1024
#define HH 1024
#define VV 10000
#define LL 2

#define MREST (127 * 64)   // 8128 rows for t = 1..127

// ---------------- scratch (device globals; no allocations allowed) ----------
__device__ float g_bufA[MREST * 1024];
__device__ float g_bufB[MREST * 1024];
__device__ float g_x0 [BB * EE];
__device__ float g_xt [BB * EE];
__device__ float g_xt2[BB * EE];
__device__ float g_h00[BB * HH];
__device__ float g_h01[BB * HH];
__device__ float g_aU0[BB * HH];
__device__ float g_aU1[BB * HH];
__device__ float g_part[4 * 64 * 10016];   // split-K partials

// ---------------- embedding gather ------------------------------------------
__global__ void gather_emb(const int* __restrict__ inputs,
                           const float* __restrict__ emb,
                           float* __restrict__ X,
                           int ioff, int nrows)
{
    int idx = blockIdx.x * blockDim.x + threadIdx.x;
    int total = nrows * 256;                // 256 float4 per row
    if (idx >= total) return;
    int r = idx >> 8;
    int c = idx & 255;
    int tok = inputs[r + ioff];
    reinterpret_cast<float4*>(X)[(size_t)r * 256 + c] =
        reinterpret_cast<const float4*>(emb)[(size_t)tok * 256 + c];
}

// =======================================================================
// Small-M (M=64) split-K fp32 GEMM (Phase A) — unchanged from R2
// =======================================================================
__global__ __launch_bounds__(256)
void sgemm_splitk(int N, int K,
                  const float* __restrict__ A,
                  const float* __restrict__ W,
                  float* __restrict__ partial)
{
    __shared__ float As[8][68];
    __shared__ float Ws[8][68];

    const int tid = threadIdx.x;
    const int bn  = blockIdx.x * 64;
    const int s   = blockIdx.y;
    const int kc  = K / gridDim.y;
    const int k0  = s * kc;

    const int tx = tid & 15;
    const int ty = tid >> 4;

    const int lr = tid >> 2;
    const int lk = (tid & 3) * 2;

    float acc[4][4];
#pragma unroll
    for (int i = 0; i < 4; i++)
#pragma unroll
        for (int j = 0; j < 4; j++) acc[i][j] = 0.0f;

    const int gn = bn + lr;
    const bool okW = gn < N;

    for (int kk = 0; kk < kc; kk += 8) {
        float2 av = *reinterpret_cast<const float2*>(&A[(size_t)lr * K + k0 + kk + lk]);
        float2 wv = make_float2(0.f, 0.f);
        if (okW)
            wv = *reinterpret_cast<const float2*>(&W[(size_t)gn * K + k0 + kk + lk]);
        As[lk][lr] = av.x;  As[lk + 1][lr] = av.y;
        Ws[lk][lr] = wv.x;  Ws[lk + 1][lr] = wv.y;
        __syncthreads();

#pragma unroll
        for (int k = 0; k < 8; k++) {
            float a[4], b[4];
#pragma unroll
            for (int i = 0; i < 4; i++) a[i] = As[k][ty * 4 + i];
#pragma unroll
            for (int j = 0; j < 4; j++) b[j] = Ws[k][tx * 4 + j];
#pragma unroll
            for (int i = 0; i < 4; i++)
#pragma unroll
                for (int j = 0; j < 4; j++)
                    acc[i][j] = fmaf(a[i], b[j], acc[i][j]);
        }
        __syncthreads();
    }

#pragma unroll
    for (int i = 0; i < 4; i++) {
        int m = ty * 4 + i;
#pragma unroll
        for (int j = 0; j < 4; j++) {
            int n = bn + tx * 4 + j;
            if (n < N)
                partial[((size_t)s * 64 + m) * N + n] = acc[i][j];
        }
    }
}

template <int EPI>
__global__ void splitk_epi(int N, int nsplit,
                           const float* __restrict__ partial,
                           const float* __restrict__ bias,
                           const float* __restrict__ aU,
                           float* __restrict__ C,
                           float* __restrict__ O,
                           int l, int row_off)
{
    int idx = blockIdx.x * blockDim.x + threadIdx.x;
    if (idx >= 64 * N) return;
    int m = idx / N;
    int n = idx - m * N;
    float acc = 0.0f;
    for (int s = 0; s < nsplit; s++)
        acc += partial[((size_t)s * 64 + m) * N + n];
    float v = acc + bias[n];
    if (EPI == 0) {
        C[(size_t)m * N + n] = v;
    } else if (EPI == 1) {
        C[(size_t)m * N + n] = tanhf(v);
    } else if (EPI == 2) {
        v += aU[(size_t)m * N + n];
        v = tanhf(v);
        C[(size_t)m * N + n] = v;
        O[(((size_t)0 * LL + l) * BB + m) * HH + n] = v;
    } else { // EPI == 3
        O[(size_t)(m + row_off) * N + n] = v;
    }
}

// =======================================================================
// Big GEMM on tensor cores (tf32 mma.sync.m16n8k8), fused epilogues
// C = A(MxK) * W(NxK)^T [+ bias / aU / tanh / dual-store]
// =======================================================================
#define TBM 128
#define TBN 128
#define TBK 16
#define TSTR 136   // stride ≡ 8 (mod 32): conflict-free fragment LDS

__device__ __forceinline__ unsigned f2tf32(float x) {
    unsigned r;
    asm("cvt.rna.tf32.f32 %0, %1;" : "=r"(r) : "f"(x));
    return r;
}

__device__ __forceinline__ void mma_tf32(float c[4], const unsigned a[4], const unsigned b[2]) {
    asm volatile("mma.sync.aligned.m16n8k8.row.col.f32.tf32.tf32.f32 "
                 "{%0,%1,%2,%3}, {%4,%5,%6,%7}, {%8,%9}, {%0,%1,%2,%3};"
                 : "+f"(c[0]), "+f"(c[1]), "+f"(c[2]), "+f"(c[3])
                 : "r"(a[0]), "r"(a[1]), "r"(a[2]), "r"(a[3]),
                   "r"(b[0]), "r"(b[1]));
}

template <int EPI>
__global__ __launch_bounds__(256)
void tgemm_nt(int M, int N, int K,
              const float* __restrict__ A,
              const float* __restrict__ W,
              const float* __restrict__ bias,
              const float* __restrict__ aU,
              float* __restrict__ C,
              float* __restrict__ O,
              int t0, int l, int row_off)
{
    __shared__ unsigned As[TBK][TSTR];
    __shared__ unsigned Ws[TBK][TSTR];

    const int tid  = threadIdx.x;
    const int lane = tid & 31;
    const int wid  = tid >> 5;
    const int wm   = (wid >> 2) * 64;   // warp M offset: 0 or 64
    const int wn   = (wid & 3) * 32;    // warp N offset: 0,32,64,96
    const int grp  = lane >> 2;         // 0..7
    const int tig  = lane & 3;          // 0..3

    const int bm = blockIdx.y * TBM;
    const int bn = blockIdx.x * TBN;

    // loaders: each thread loads 2 float4 per matrix per tile
    const int ldr = tid >> 1;           // 0..127
    const int ldk = (tid & 1) * 8;      // 0 or 8

    const int gmA = bm + ldr;
    const int gnW = bn + ldr;
    const bool okA = gmA < M;
    const bool okW = gnW < N;
    const float* Ap = A + (size_t)(okA ? gmA : 0) * K + ldk;
    const float* Wp = W + (size_t)(okW ? gnW : 0) * K + ldk;
    const float4 z4 = make_float4(0.f, 0.f, 0.f, 0.f);

    float4 va0 = okA ? *reinterpret_cast<const float4*>(Ap)     : z4;
    float4 va1 = okA ? *reinterpret_cast<const float4*>(Ap + 4) : z4;
    float4 vw0 = okW ? *reinterpret_cast<const float4*>(Wp)     : z4;
    float4 vw1 = okW ? *reinterpret_cast<const float4*>(Wp + 4) : z4;

    float acc[4][4][4];
#pragma unroll
    for (int mf = 0; mf < 4; mf++)
#pragma unroll
        for (int nf = 0; nf < 4; nf++)
#pragma unroll
            for (int r = 0; r < 4; r++) acc[mf][nf][r] = 0.0f;

    for (int k0 = 0; k0 < K; k0 += TBK) {
        As[ldk + 0][ldr] = f2tf32(va0.x);
        As[ldk + 1][ldr] = f2tf32(va0.y);
        As[ldk + 2][ldr] = f2tf32(va0.z);
        As[ldk + 3][ldr] = f2tf32(va0.w);
        As[ldk + 4][ldr] = f2tf32(va1.x);
        As[ldk + 5][ldr] = f2tf32(va1.y);
        As[ldk + 6][ldr] = f2tf32(va1.z);
        As[ldk + 7][ldr] = f2tf32(va1.w);
        Ws[ldk + 0][ldr] = f2tf32(vw0.x);
        Ws[ldk + 1][ldr] = f2tf32(vw0.y);
        Ws[ldk + 2][ldr] = f2tf32(vw0.z);
        Ws[ldk + 3][ldr] = f2tf32(vw0.w);
        Ws[ldk + 4][ldr] = f2tf32(vw1.x);
        Ws[ldk + 5][ldr] = f2tf32(vw1.y);
        Ws[ldk + 6][ldr] = f2tf32(vw1.z);
        Ws[ldk + 7][ldr] = f2tf32(vw1.w);
        __syncthreads();

        if (k0 + TBK < K) {   // prefetch next tile into registers
            va0 = okA ? *reinterpret_cast<const float4*>(Ap + k0 + TBK)     : z4;
            va1 = okA ? *reinterpret_cast<const float4*>(Ap + k0 + TBK + 4) : z4;
            vw0 = okW ? *reinterpret_cast<const float4*>(Wp + k0 + TBK)     : z4;
            vw1 = okW ? *reinterpret_cast<const float4*>(Wp + k0 + TBK + 4) : z4;
        }

#pragma unroll
        for (int ks = 0; ks < TBK; ks += 8) {
            unsigned af[4][4], bf[4][2];
#pragma unroll
            for (int mf = 0; mf < 4; mf++) {
                int r0 = wm + mf * 16 + grp;
                af[mf][0] = As[ks + tig][r0];
                af[mf][1] = As[ks + tig][r0 + 8];
                af[mf][2] = As[ks + tig + 4][r0];
                af[mf][3] = As[ks + tig + 4][r0 + 8];
            }
#pragma unroll
            for (int nf = 0; nf < 4; nf++) {
                int c0 = wn + nf * 8 + grp;
                bf[nf][0] = Ws[ks + tig][c0];
                bf[nf][1] = Ws[ks + tig + 4][c0];
            }
#pragma unroll
            for (int mf = 0; mf < 4; mf++)
#pragma unroll
                for (int nf = 0; nf < 4; nf++)
                    mma_tf32(acc[mf][nf], af[mf], bf[nf]);
        }
        __syncthreads();
    }

    // epilogue: c0,c1 -> (row grp, cols tig*2, tig*2+1); c2,c3 -> row grp+8
#pragma unroll
    for (int mf = 0; mf < 4; mf++) {
#pragma unroll
        for (int rh = 0; rh < 2; rh++) {          // row half (grp / grp+8)
            int gm = bm + wm + mf * 16 + grp + rh * 8;
            if (gm >= M) continue;
#pragma unroll
            for (int nf = 0; nf < 4; nf++) {
                int gn = bn + wn + nf * 8 + tig * 2;
                if (gn >= N) continue;            // N even → gn+1 < N too
                float v0 = acc[mf][nf][rh * 2 + 0] + bias[gn];
                float v1 = acc[mf][nf][rh * 2 + 1] + bias[gn + 1];
                if (EPI == 1) {
                    v0 = tanhf(v0); v1 = tanhf(v1);
                    *reinterpret_cast<float2*>(&C[(size_t)gm * N + gn]) =
                        make_float2(v0, v1);
                } else if (EPI == 2) {
                    const float2 au = *reinterpret_cast<const float2*>(
                        &aU[(size_t)(gm & 63) * N + gn]);
                    v0 = tanhf(v0 + au.x);
                    v1 = tanhf(v1 + au.y);
                    *reinterpret_cast<float2*>(&C[(size_t)gm * N + gn]) =
                        make_float2(v0, v1);
                    int t = t0 + (gm >> 6);
                    int b = gm & 63;
                    *reinterpret_cast<float2*>(
                        &O[(((size_t)t * LL + l) * BB + b) * HH + gn]) =
                        make_float2(v0, v1);
                } else { // EPI == 3 (logits)
                    *reinterpret_cast<float2*>(&O[(size_t)(gm + row_off) * N + gn]) =
                        make_float2(v0, v1);
                }
            }
        }
    }
}

// ---------------- host-side orchestration -----------------------------------
static inline dim3 tgrid(int M, int N) {
    return dim3((N + TBN - 1) / TBN, (M + TBM - 1) / TBM);
}

template <int EPI>
static void small_gemm(int N, int K, int nsplit,
                       const float* A, const float* W, const float* bias,
                       const float* aU, float* C, float* O,
                       int l, int row_off, float* part)
{
    dim3 g((N + 63) / 64, nsplit);
    sgemm_splitk<<<g, 256>>>(N, K, A, W, part);
    int total = 64 * N;
    splitk_epi<EPI><<<(total + 255) / 256, 256>>>(N, nsplit, part, bias, aU, C, O, l, row_off);
}

extern "C" void kernel_launch(void* const* d_in, const int* in_sizes, int n_in,
                              void* d_out, int out_size)
{
    (void)in_sizes; (void)n_in; (void)out_size;
    const int*   inputs = (const int*)  d_in[0];
    const float* hidden = (const float*)d_in[1];   // (L,B,H)
    const float* emb    = (const float*)d_in[2];   // (V,E)
    const float* Ww     = (const float*)d_in[3];   // (L,H,E)
    const float* Wb     = (const float*)d_in[4];   // (L,H)
    const float* Uw     = (const float*)d_in[5];   // (L,H,H)
    const float* Ub     = (const float*)d_in[6];   // (L,H)
    const float* Fw     = (const float*)d_in[7];   // (L,E,H)
    const float* Fb     = (const float*)d_in[8];   // (L,E)
    const float* Dw     = (const float*)d_in[9];   // (V,H)
    const float* Db     = (const float*)d_in[10];  // (V,)

    float* out  = (float*)d_out;
    float* hall = out + (size_t)TT * BB * VV;      // h_all after logits

    float *bufA, *bufB, *x0, *xt, *xt2, *h00, *h01, *aU0, *aU1, *part;
    cudaGetSymbolAddress((void**)&bufA, g_bufA);
    cudaGetSymbolAddress((void**)&bufB, g_bufB);
    cudaGetSymbolAddress((void**)&x0,  g_x0);
    cudaGetSymbolAddress((void**)&xt,  g_xt);
    cudaGetSymbolAddress((void**)&xt2, g_xt2);
    cudaGetSymbolAddress((void**)&h00, g_h00);
    cudaGetSymbolAddress((void**)&h01, g_h01);
    cudaGetSymbolAddress((void**)&aU0, g_aU0);
    cudaGetSymbolAddress((void**)&aU1, g_aU1);
    cudaGetSymbolAddress((void**)&part, g_part);

    const size_t Wstride = (size_t)HH * EE;

    // ---- Phase A: t = 0 (sequential small GEMMs, M = 64, split-K fp32) ----
    gather_emb<<<(BB * 256 + 255) / 256, 256>>>(inputs, emb, x0, 0, BB);

    small_gemm<0>(HH, HH, 16, hidden, Uw, Ub, nullptr, aU0, nullptr, 0, 0, part);
    small_gemm<2>(HH, EE, 16, x0, Ww, Wb, aU0, h00, hall, 0, 0, part);
    small_gemm<1>(EE, HH, 16, h00, Fw, Fb, nullptr, xt, nullptr, 0, 0, part);
    small_gemm<0>(HH, HH, 16, hidden + (size_t)BB * HH, Uw + Wstride, Ub + HH,
                  nullptr, aU1, nullptr, 0, 0, part);
    small_gemm<2>(HH, EE, 16, xt, Ww + Wstride, Wb + HH, aU1, h01, hall, 1, 0, part);
    small_gemm<1>(EE, HH, 16, h01, Fw + Wstride, Fb + EE, nullptr, xt2, nullptr, 0, 0, part);
    small_gemm<3>(VV, HH, 4, xt2, Dw, Db, nullptr, nullptr, out, 0, 0, part);

    // ---- fixed recurrent terms for t >= 1 ----
    small_gemm<0>(HH, HH, 16, h00, Uw, Ub, nullptr, aU0, nullptr, 0, 0, part);
    small_gemm<0>(HH, HH, 16, h01, Uw + Wstride, Ub + HH, nullptr, aU1, nullptr, 0, 0, part);

    // ---- Phase B: t = 1..127 batched (M = 8128) on tensor cores ----
    gather_emb<<<(MREST * 256 + 255) / 256, 256>>>(inputs, emb, bufA, BB, MREST);

    tgemm_nt<2><<<tgrid(MREST, HH), 256>>>(MREST, HH, EE, bufA, Ww, Wb,
                                           aU0, bufB, hall, 1, 0, 0);
    tgemm_nt<1><<<tgrid(MREST, EE), 256>>>(MREST, EE, HH, bufB, Fw, Fb,
                                           nullptr, bufA, nullptr, 0, 0, 0);
    tgemm_nt<2><<<tgrid(MREST, HH), 256>>>(MREST, HH, EE, bufA,
                                           Ww + Wstride, Wb + HH,
                                           aU1, bufB, hall, 1, 1, 0);
    tgemm_nt<1><<<tgrid(MREST, EE), 256>>>(MREST, EE, HH, bufB,
                                           Fw + Wstride, Fb + EE,
                                           nullptr, bufA, nullptr, 0, 0, 0);
    tgemm_nt<3><<<tgrid(MREST, VV), 256>>>(MREST, VV, HH, bufA, Dw, Db,
                                           nullptr, nullptr, out, 0, 0, BB);
}

// round 4
// speedup vs baseline: 3.7326x; 1.3370x over previous
#include <cuda_runtime.h>
#include <cstddef>
#include <cstdint>

// Problem constants (fixed by the dataset)
#define TT 128
#define BB 64
#define EE 1024
#define HH 1024
#define VV 10000
#define LL 2

#define MREST (127 * 64)   // 8128 rows for t = 1..127

// ---------------- scratch (device globals; no allocations allowed) ----------
__device__ float g_bufA[MREST * 1024];
__device__ float g_bufB[MREST * 1024];
__device__ float g_x0 [BB * EE];
__device__ float g_xt [BB * EE];
__device__ float g_xt2[BB * EE];
__device__ float g_h00[BB * HH];
__device__ float g_h01[BB * HH];
__device__ float g_aU0[BB * HH];
__device__ float g_aU1[BB * HH];
__device__ float g_part[4 * 64 * 10016];       // split-K partials
__device__ float g_WwR[LL * HH * EE];          // tf32-rounded weights
__device__ float g_FwR[LL * EE * HH];
__device__ float g_DwR[VV * HH];

// ---------------- tf32 rounding helper --------------------------------------
__device__ __forceinline__ float round_tf32f(float x) {
    unsigned r;
    asm("cvt.rna.tf32.f32 %0, %1;" : "=r"(r) : "f"(x));
    return __uint_as_float(r);
}

// pre-round a weight tensor to tf32 (vectorized, 4 per thread)
__global__ void round_tf32_kernel(const float* __restrict__ src,
                                  float* __restrict__ dst, int n4)
{
    int i = blockIdx.x * blockDim.x + threadIdx.x;
    if (i >= n4) return;
    float4 v = reinterpret_cast<const float4*>(src)[i];
    v.x = round_tf32f(v.x); v.y = round_tf32f(v.y);
    v.z = round_tf32f(v.z); v.w = round_tf32f(v.w);
    reinterpret_cast<float4*>(dst)[i] = v;
}

// ---------------- embedding gather (optional tf32 rounding) ------------------
__global__ void gather_emb(const int* __restrict__ inputs,
                           const float* __restrict__ emb,
                           float* __restrict__ X,
                           int ioff, int nrows, int do_round)
{
    int idx = blockIdx.x * blockDim.x + threadIdx.x;
    int total = nrows * 256;                // 256 float4 per row
    if (idx >= total) return;
    int r = idx >> 8;
    int c = idx & 255;
    int tok = inputs[r + ioff];
    float4 v = reinterpret_cast<const float4*>(emb)[(size_t)tok * 256 + c];
    if (do_round) {
        v.x = round_tf32f(v.x); v.y = round_tf32f(v.y);
        v.z = round_tf32f(v.z); v.w = round_tf32f(v.w);
    }
    reinterpret_cast<float4*>(X)[(size_t)r * 256 + c] = v;
}

// =======================================================================
// Small-M (M=64) split-K fp32 GEMM (Phase A)
// =======================================================================
__global__ __launch_bounds__(256)
void sgemm_splitk(int N, int K,
                  const float* __restrict__ A,
                  const float* __restrict__ W,
                  float* __restrict__ partial)
{
    __shared__ float As[8][68];
    __shared__ float Ws[8][68];

    const int tid = threadIdx.x;
    const int bn  = blockIdx.x * 64;
    const int s   = blockIdx.y;
    const int kc  = K / gridDim.y;
    const int k0  = s * kc;

    const int tx = tid & 15;
    const int ty = tid >> 4;

    const int lr = tid >> 2;
    const int lk = (tid & 3) * 2;

    float acc[4][4];
#pragma unroll
    for (int i = 0; i < 4; i++)
#pragma unroll
        for (int j = 0; j < 4; j++) acc[i][j] = 0.0f;

    const int gn = bn + lr;
    const bool okW = gn < N;

    for (int kk = 0; kk < kc; kk += 8) {
        float2 av = *reinterpret_cast<const float2*>(&A[(size_t)lr * K + k0 + kk + lk]);
        float2 wv = make_float2(0.f, 0.f);
        if (okW)
            wv = *reinterpret_cast<const float2*>(&W[(size_t)gn * K + k0 + kk + lk]);
        As[lk][lr] = av.x;  As[lk + 1][lr] = av.y;
        Ws[lk][lr] = wv.x;  Ws[lk + 1][lr] = wv.y;
        __syncthreads();

#pragma unroll
        for (int k = 0; k < 8; k++) {
            float a[4], b[4];
#pragma unroll
            for (int i = 0; i < 4; i++) a[i] = As[k][ty * 4 + i];
#pragma unroll
            for (int j = 0; j < 4; j++) b[j] = Ws[k][tx * 4 + j];
#pragma unroll
            for (int i = 0; i < 4; i++)
#pragma unroll
                for (int j = 0; j < 4; j++)
                    acc[i][j] = fmaf(a[i], b[j], acc[i][j]);
        }
        __syncthreads();
    }

#pragma unroll
    for (int i = 0; i < 4; i++) {
        int m = ty * 4 + i;
#pragma unroll
        for (int j = 0; j < 4; j++) {
            int n = bn + tx * 4 + j;
            if (n < N)
                partial[((size_t)s * 64 + m) * N + n] = acc[i][j];
        }
    }
}

template <int EPI>
__global__ void splitk_epi(int N, int nsplit,
                           const float* __restrict__ partial,
                           const float* __restrict__ bias,
                           const float* __restrict__ aU,
                           float* __restrict__ C,
                           float* __restrict__ O,
                           int l, int row_off)
{
    int idx = blockIdx.x * blockDim.x + threadIdx.x;
    if (idx >= 64 * N) return;
    int m = idx / N;
    int n = idx - m * N;
    float acc = 0.0f;
    for (int s = 0; s < nsplit; s++)
        acc += partial[((size_t)s * 64 + m) * N + n];
    float v = acc + bias[n];
    if (EPI == 0) {
        C[(size_t)m * N + n] = v;
    } else if (EPI == 1) {
        C[(size_t)m * N + n] = tanhf(v);
    } else if (EPI == 2) {
        v += aU[(size_t)m * N + n];
        v = tanhf(v);
        C[(size_t)m * N + n] = v;
        O[(((size_t)0 * LL + l) * BB + m) * HH + n] = v;
    } else { // EPI == 3
        O[(size_t)(m + row_off) * N + n] = v;
    }
}

// =======================================================================
// Big GEMM on tensor cores: tf32 mma.sync, cp.async double-buffered,
// 128x256 block tile, 8 warps of 64x64. Inputs must be pre-rounded tf32.
// =======================================================================
#define CBM 128
#define CBN 256
#define CBK 16
#define ASTR 20                       // row stride in floats (conflict-free)
#define ABUF_FLOATS (CBM * ASTR)      // 2560
#define WBUF_FLOATS (CBN * ASTR)      // 5120
#define SMEM_BYTES ((2 * ABUF_FLOATS + 2 * WBUF_FLOATS) * 4)   // 61440

__device__ __forceinline__ void cp_async16(uint32_t saddr, const void* gptr, bool ok) {
    int sz = ok ? 16 : 0;
    asm volatile("cp.async.cg.shared.global [%0], [%1], 16, %2;\n"
                 :: "r"(saddr), "l"(gptr), "r"(sz));
}

__device__ __forceinline__ void mma_tf32(float c[4], const unsigned a[4], const unsigned b[2]) {
    asm volatile("mma.sync.aligned.m16n8k8.row.col.f32.tf32.tf32.f32 "
                 "{%0,%1,%2,%3}, {%4,%5,%6,%7}, {%8,%9}, {%0,%1,%2,%3};"
                 : "+f"(c[0]), "+f"(c[1]), "+f"(c[2]), "+f"(c[3])
                 : "r"(a[0]), "r"(a[1]), "r"(a[2]), "r"(a[3]),
                   "r"(b[0]), "r"(b[1]));
}

template <int EPI>
__global__ __launch_bounds__(256, 1)
void tgemm2(int M, int N, int K,
            const float* __restrict__ A,
            const float* __restrict__ W,
            const float* __restrict__ bias,
            const float* __restrict__ aU,
            float* __restrict__ C,
            float* __restrict__ O,
            int t0, int l, int row_off)
{
    extern __shared__ float sm[];

    const int tid  = threadIdx.x;
    const int lane = tid & 31;
    const int wid  = tid >> 5;
    const int wm   = (wid & 1) * 64;     // warp M offset
    const int wn   = (wid >> 1) * 64;    // warp N offset
    const int grp  = lane >> 2;
    const int tig  = lane & 3;

    const int bm = blockIdx.y * CBM;
    const int bn = blockIdx.x * CBN;

    uint32_t sbase;
    asm("{ .reg .u64 t; cvta.to.shared.u64 t, %1; cvt.u32.u64 %0, t; }"
        : "=r"(sbase) : "l"(sm));

    // ---- loader setup: A 2 float4 slots, W 4 float4 slots per thread ----
    const int ar0 = tid >> 1;                 // wrong granularity? no: slots below
    (void)ar0;
    int arow[2], aseg[2];  bool aok[2];  const float* agp[2];  uint32_t asm_[2];
#pragma unroll
    for (int i = 0; i < 2; i++) {
        int slot = tid + 256 * i;
        arow[i] = slot >> 2;
        aseg[i] = (slot & 3) * 4;
        aok[i]  = (bm + arow[i]) < M;
        agp[i]  = A + (size_t)(aok[i] ? bm + arow[i] : 0) * K + aseg[i];
        asm_[i] = sbase + (uint32_t)(arow[i] * ASTR + aseg[i]) * 4;
    }
    int wrow[4], wseg[4];  bool wok[4];  const float* wgp[4];  uint32_t wsm_[4];
#pragma unroll
    for (int i = 0; i < 4; i++) {
        int slot = tid + 256 * i;
        wrow[i] = slot >> 2;
        wseg[i] = (slot & 3) * 4;
        wok[i]  = (bn + wrow[i]) < N;
        wgp[i]  = W + (size_t)(wok[i] ? bn + wrow[i] : 0) * K + wseg[i];
        wsm_[i] = sbase + (uint32_t)(2 * ABUF_FLOATS + wrow[i] * ASTR + wseg[i]) * 4;
    }

    float acc[4][8][4];
#pragma unroll
    for (int mf = 0; mf < 4; mf++)
#pragma unroll
        for (int nf = 0; nf < 8; nf++)
#pragma unroll
            for (int r = 0; r < 4; r++) acc[mf][nf][r] = 0.0f;

    const int kT = K / CBK;

    // prologue: load tile 0 into buffer 0
#pragma unroll
    for (int i = 0; i < 2; i++) cp_async16(asm_[i], agp[i], aok[i]);
#pragma unroll
    for (int i = 0; i < 4; i++) cp_async16(wsm_[i] , wgp[i], wok[i]);
    asm volatile("cp.async.commit_group;\n");

    for (int kt = 0; kt < kT; kt++) {
        const int cb = kt & 1;
        if (kt + 1 < kT) {
            const int nb = cb ^ 1;
            const int koff = (kt + 1) * CBK;
#pragma unroll
            for (int i = 0; i < 2; i++)
                cp_async16(asm_[i] + nb * (ABUF_FLOATS * 4), agp[i] + koff, aok[i]);
#pragma unroll
            for (int i = 0; i < 4; i++)
                cp_async16(wsm_[i] + nb * (WBUF_FLOATS * 4), wgp[i] + koff, wok[i]);
        }
        asm volatile("cp.async.commit_group;\n");
        asm volatile("cp.async.wait_group 1;\n");
        __syncthreads();

        const float* Ab = sm + cb * ABUF_FLOATS;
        const float* Wb = sm + 2 * ABUF_FLOATS + cb * WBUF_FLOATS;

#pragma unroll
        for (int ks = 0; ks < CBK; ks += 8) {
            unsigned af[4][4], bf[8][2];
#pragma unroll
            for (int mf = 0; mf < 4; mf++) {
                int r0 = wm + mf * 16 + grp;
                af[mf][0] = __float_as_uint(Ab[r0 * ASTR + ks + tig]);
                af[mf][1] = __float_as_uint(Ab[(r0 + 8) * ASTR + ks + tig]);
                af[mf][2] = __float_as_uint(Ab[r0 * ASTR + ks + tig + 4]);
                af[mf][3] = __float_as_uint(Ab[(r0 + 8) * ASTR + ks + tig + 4]);
            }
#pragma unroll
            for (int nf = 0; nf < 8; nf++) {
                int c0 = wn + nf * 8 + grp;
                bf[nf][0] = __float_as_uint(Wb[c0 * ASTR + ks + tig]);
                bf[nf][1] = __float_as_uint(Wb[c0 * ASTR + ks + tig + 4]);
            }
#pragma unroll
            for (int mf = 0; mf < 4; mf++)
#pragma unroll
                for (int nf = 0; nf < 8; nf++)
                    mma_tf32(acc[mf][nf], af[mf], bf[nf]);
        }
        __syncthreads();
    }

    // ---- epilogue ----
#pragma unroll
    for (int mf = 0; mf < 4; mf++) {
#pragma unroll
        for (int rh = 0; rh < 2; rh++) {
            int gm = bm + wm + mf * 16 + grp + rh * 8;
            if (gm >= M) continue;
#pragma unroll
            for (int nf = 0; nf < 8; nf++) {
                int gn = bn + wn + nf * 8 + tig * 2;
                if (gn >= N) continue;            // N even → gn+1 ok
                float v0 = acc[mf][nf][rh * 2 + 0] + bias[gn];
                float v1 = acc[mf][nf][rh * 2 + 1] + bias[gn + 1];
                if (EPI == 1) {
                    v0 = tanhf(v0); v1 = tanhf(v1);
                    // C feeds the next tf32 GEMM: store rounded
                    *reinterpret_cast<float2*>(&C[(size_t)gm * N + gn]) =
                        make_float2(round_tf32f(v0), round_tf32f(v1));
                } else if (EPI == 2) {
                    const float2 au = *reinterpret_cast<const float2*>(
                        &aU[(size_t)(gm & 63) * N + gn]);
                    v0 = tanhf(v0 + au.x);
                    v1 = tanhf(v1 + au.y);
                    *reinterpret_cast<float2*>(&C[(size_t)gm * N + gn]) =
                        make_float2(round_tf32f(v0), round_tf32f(v1));
                    int t = t0 + (gm >> 6);
                    int b = gm & 63;
                    *reinterpret_cast<float2*>(
                        &O[(((size_t)t * LL + l) * BB + b) * HH + gn]) =
                        make_float2(v0, v1);      // h_all output: exact tanh
                } else { // EPI == 3 (logits, exact)
                    *reinterpret_cast<float2*>(&O[(size_t)(gm + row_off) * N + gn]) =
                        make_float2(v0, v1);
                }
            }
        }
    }
}

// ---------------- host-side orchestration -----------------------------------
static inline dim3 tgrid2(int M, int N) {
    return dim3((N + CBN - 1) / CBN, (M + CBM - 1) / CBM);
}

template <int EPI>
static void small_gemm(int N, int K, int nsplit,
                       const float* A, const float* W, const float* bias,
                       const float* aU, float* C, float* O,
                       int l, int row_off, float* part)
{
    dim3 g((N + 63) / 64, nsplit);
    sgemm_splitk<<<g, 256>>>(N, K, A, W, part);
    int total = 64 * N;
    splitk_epi<EPI><<<(total + 255) / 256, 256>>>(N, nsplit, part, bias, aU, C, O, l, row_off);
}

extern "C" void kernel_launch(void* const* d_in, const int* in_sizes, int n_in,
                              void* d_out, int out_size)
{
    (void)in_sizes; (void)n_in; (void)out_size;
    const int*   inputs = (const int*)  d_in[0];
    const float* hidden = (const float*)d_in[1];   // (L,B,H)
    const float* emb    = (const float*)d_in[2];   // (V,E)
    const float* Ww     = (const float*)d_in[3];   // (L,H,E)
    const float* Wb     = (const float*)d_in[4];   // (L,H)
    const float* Uw     = (const float*)d_in[5];   // (L,H,H)
    const float* Ub     = (const float*)d_in[6];   // (L,H)
    const float* Fw     = (const float*)d_in[7];   // (L,E,H)
    const float* Fb     = (const float*)d_in[8];   // (L,E)
    const float* Dw     = (const float*)d_in[9];   // (V,H)
    const float* Db     = (const float*)d_in[10];  // (V,)

    float* out  = (float*)d_out;
    float* hall = out + (size_t)TT * BB * VV;      // h_all after logits

    float *bufA, *bufB, *x0, *xt, *xt2, *h00, *h01, *aU0, *aU1, *part;
    float *WwR, *FwR, *DwR;
    cudaGetSymbolAddress((void**)&bufA, g_bufA);
    cudaGetSymbolAddress((void**)&bufB, g_bufB);
    cudaGetSymbolAddress((void**)&x0,  g_x0);
    cudaGetSymbolAddress((void**)&xt,  g_xt);
    cudaGetSymbolAddress((void**)&xt2, g_xt2);
    cudaGetSymbolAddress((void**)&h00, g_h00);
    cudaGetSymbolAddress((void**)&h01, g_h01);
    cudaGetSymbolAddress((void**)&aU0, g_aU0);
    cudaGetSymbolAddress((void**)&aU1, g_aU1);
    cudaGetSymbolAddress((void**)&part, g_part);
    cudaGetSymbolAddress((void**)&WwR, g_WwR);
    cudaGetSymbolAddress((void**)&FwR, g_FwR);
    cudaGetSymbolAddress((void**)&DwR, g_DwR);

    // allow 60KB dynamic smem on the tensor GEMM instantiations
    cudaFuncSetAttribute(tgemm2<1>, cudaFuncAttributeMaxDynamicSharedMemorySize, SMEM_BYTES);
    cudaFuncSetAttribute(tgemm2<2>, cudaFuncAttributeMaxDynamicSharedMemorySize, SMEM_BYTES);
    cudaFuncSetAttribute(tgemm2<3>, cudaFuncAttributeMaxDynamicSharedMemorySize, SMEM_BYTES);

    const size_t Wstride = (size_t)HH * EE;

    // ---- pre-round weights to tf32 (overlappable with Phase A deps) ----
    {
        int n4;
        n4 = (LL * HH * EE) / 4;
        round_tf32_kernel<<<(n4 + 255) / 256, 256>>>(Ww, WwR, n4);
        n4 = (LL * EE * HH) / 4;
        round_tf32_kernel<<<(n4 + 255) / 256, 256>>>(Fw, FwR, n4);
        n4 = (VV * HH) / 4;
        round_tf32_kernel<<<(n4 + 255) / 256, 256>>>(Dw, DwR, n4);
    }

    // ---- Phase A: t = 0 (sequential small GEMMs, M = 64, split-K fp32) ----
    gather_emb<<<(BB * 256 + 255) / 256, 256>>>(inputs, emb, x0, 0, BB, 0);

    small_gemm<0>(HH, HH, 16, hidden, Uw, Ub, nullptr, aU0, nullptr, 0, 0, part);
    small_gemm<2>(HH, EE, 16, x0, Ww, Wb, aU0, h00, hall, 0, 0, part);
    small_gemm<1>(EE, HH, 16, h00, Fw, Fb, nullptr, xt, nullptr, 0, 0, part);
    small_gemm<0>(HH, HH, 16, hidden + (size_t)BB * HH, Uw + Wstride, Ub + HH,
                  nullptr, aU1, nullptr, 0, 0, part);
    small_gemm<2>(HH, EE, 16, xt, Ww + Wstride, Wb + HH, aU1, h01, hall, 1, 0, part);
    small_gemm<1>(EE, HH, 16, h01, Fw + Wstride, Fb + EE, nullptr, xt2, nullptr, 0, 0, part);
    small_gemm<3>(VV, HH, 4, xt2, Dw, Db, nullptr, nullptr, out, 0, 0, part);

    // ---- fixed recurrent terms for t >= 1 ----
    small_gemm<0>(HH, HH, 16, h00, Uw, Ub, nullptr, aU0, nullptr, 0, 0, part);
    small_gemm<0>(HH, HH, 16, h01, Uw + Wstride, Ub + HH, nullptr, aU1, nullptr, 0, 0, part);

    // ---- Phase B: t = 1..127 batched (M = 8128) on tensor cores ----
    gather_emb<<<(MREST * 256 + 255) / 256, 256>>>(inputs, emb, bufA, BB, MREST, 1);

    tgemm2<2><<<tgrid2(MREST, HH), 256, SMEM_BYTES>>>(MREST, HH, EE, bufA, WwR, Wb,
                                                      aU0, bufB, hall, 1, 0, 0);
    tgemm2<1><<<tgrid2(MREST, EE), 256, SMEM_BYTES>>>(MREST, EE, HH, bufB, FwR, Fb,
                                                      nullptr, bufA, nullptr, 0, 0, 0);
    tgemm2<2><<<tgrid2(MREST, HH), 256, SMEM_BYTES>>>(MREST, HH, EE, bufA,
                                                      WwR + Wstride, Wb + HH,
                                                      aU1, bufB, hall, 1, 1, 0);
    tgemm2<1><<<tgrid2(MREST, EE), 256, SMEM_BYTES>>>(MREST, EE, HH, bufB,
                                                      FwR + Wstride, Fb + EE,
                                                      nullptr, bufA, nullptr, 0, 0, 0);
    tgemm2<3><<<tgrid2(MREST, VV), 256, SMEM_BYTES>>>(MREST, VV, HH, bufA, DwR, Db,
                                                      nullptr, nullptr, out, 0, 0, BB);
}

// round 5
// speedup vs baseline: 3.7823x; 1.0133x over previous
#include <cuda_runtime.h>
#include <cstddef>
#include <cstdint>

// Problem constants (fixed by the dataset)
#define TT 128
#define BB 64
#define EE 1024
#define HH 1024
#define VV 10000
#define LL 2

#define MREST (127 * 64)   // 8128 rows for t = 1..127

// ---------------- scratch (device globals; no allocations allowed) ----------
__device__ float g_bufA[MREST * 1024];
__device__ float g_bufB[MREST * 1024];
__device__ float g_x0 [BB * EE];
__device__ float g_xt [BB * EE];
__device__ float g_xt2[BB * EE];
__device__ float g_h0 [2 * BB * HH];           // h00 | h01
__device__ float g_aU [2 * BB * HH];           // aU0 | aU1
__device__ float g_part[4 * 64 * 10016];       // split-K partials
__device__ float g_WwR[LL * HH * EE];          // tf32-rounded weights
__device__ float g_FwR[LL * EE * HH];
__device__ float g_DwR[VV * HH];

// ---------------- tf32 rounding helper --------------------------------------
__device__ __forceinline__ float round_tf32f(float x) {
    unsigned r;
    asm("cvt.rna.tf32.f32 %0, %1;" : "=r"(r) : "f"(x));
    return __uint_as_float(r);
}

__global__ void round_tf32_kernel(const float* __restrict__ src,
                                  float* __restrict__ dst, int n4)
{
    int i = blockIdx.x * blockDim.x + threadIdx.x;
    if (i >= n4) return;
    float4 v = reinterpret_cast<const float4*>(src)[i];
    v.x = round_tf32f(v.x); v.y = round_tf32f(v.y);
    v.z = round_tf32f(v.z); v.w = round_tf32f(v.w);
    reinterpret_cast<float4*>(dst)[i] = v;
}

// ---------------- embedding gather (optional tf32 rounding) ------------------
__global__ void gather_emb(const int* __restrict__ inputs,
                           const float* __restrict__ emb,
                           float* __restrict__ X,
                           int ioff, int nrows, int do_round)
{
    int idx = blockIdx.x * blockDim.x + threadIdx.x;
    int total = nrows * 256;                // 256 float4 per row
    if (idx >= total) return;
    int r = idx >> 8;
    int c = idx & 255;
    int tok = inputs[r + ioff];
    float4 v = reinterpret_cast<const float4*>(emb)[(size_t)tok * 256 + c];
    if (do_round) {
        v.x = round_tf32f(v.x); v.y = round_tf32f(v.y);
        v.z = round_tf32f(v.z); v.w = round_tf32f(v.w);
    }
    reinterpret_cast<float4*>(X)[(size_t)r * 256 + c] = v;
}

// =======================================================================
// Small-M (M=64) split-K fp32 GEMM (Phase A), batchable via grid.z
// =======================================================================
__global__ __launch_bounds__(256)
void sgemm_splitk(int N, int K,
                  const float* __restrict__ A,
                  const float* __restrict__ W,
                  float* __restrict__ partial,
                  size_t aStride, size_t wStride, size_t pStride)
{
    const float* Ab = A + blockIdx.z * aStride;
    const float* Wb = W + blockIdx.z * wStride;
    float* Pb = partial + blockIdx.z * pStride;

    __shared__ float As[8][68];
    __shared__ float Ws[8][68];

    const int tid = threadIdx.x;
    const int bn  = blockIdx.x * 64;
    const int s   = blockIdx.y;
    const int kc  = K / gridDim.y;
    const int k0  = s * kc;

    const int tx = tid & 15;
    const int ty = tid >> 4;

    const int lr = tid >> 2;
    const int lk = (tid & 3) * 2;

    float acc[4][4];
#pragma unroll
    for (int i = 0; i < 4; i++)
#pragma unroll
        for (int j = 0; j < 4; j++) acc[i][j] = 0.0f;

    const int gn = bn + lr;
    const bool okW = gn < N;

    for (int kk = 0; kk < kc; kk += 8) {
        float2 av = *reinterpret_cast<const float2*>(&Ab[(size_t)lr * K + k0 + kk + lk]);
        float2 wv = make_float2(0.f, 0.f);
        if (okW)
            wv = *reinterpret_cast<const float2*>(&Wb[(size_t)gn * K + k0 + kk + lk]);
        As[lk][lr] = av.x;  As[lk + 1][lr] = av.y;
        Ws[lk][lr] = wv.x;  Ws[lk + 1][lr] = wv.y;
        __syncthreads();

#pragma unroll
        for (int k = 0; k < 8; k++) {
            float a[4], b[4];
#pragma unroll
            for (int i = 0; i < 4; i++) a[i] = As[k][ty * 4 + i];
#pragma unroll
            for (int j = 0; j < 4; j++) b[j] = Ws[k][tx * 4 + j];
#pragma unroll
            for (int i = 0; i < 4; i++)
#pragma unroll
                for (int j = 0; j < 4; j++)
                    acc[i][j] = fmaf(a[i], b[j], acc[i][j]);
        }
        __syncthreads();
    }

#pragma unroll
    for (int i = 0; i < 4; i++) {
        int m = ty * 4 + i;
#pragma unroll
        for (int j = 0; j < 4; j++) {
            int n = bn + tx * 4 + j;
            if (n < N)
                Pb[((size_t)s * 64 + m) * N + n] = acc[i][j];
        }
    }
}

// reduce + epilogue; batched over blockIdx.y (EPI 0 only uses batching)
template <int EPI>
__global__ void splitk_epi(int N, int nsplit,
                           const float* __restrict__ partial,
                           const float* __restrict__ bias,
                           const float* __restrict__ aU,
                           float* __restrict__ C,
                           float* __restrict__ O,
                           int l, int row_off,
                           size_t pStride, size_t bStride, size_t cStride)
{
    const float* Pb = partial + blockIdx.y * pStride;
    const float* Bb = bias + blockIdx.y * bStride;
    float* Cb = C ? C + blockIdx.y * cStride : nullptr;

    int idx = blockIdx.x * blockDim.x + threadIdx.x;
    if (idx >= 64 * N) return;
    int m = idx / N;
    int n = idx - m * N;
    float acc = 0.0f;
    for (int s = 0; s < nsplit; s++)
        acc += Pb[((size_t)s * 64 + m) * N + n];
    float v = acc + Bb[n];
    if (EPI == 0) {
        Cb[(size_t)m * N + n] = v;
    } else if (EPI == 1) {
        Cb[(size_t)m * N + n] = tanhf(v);
    } else if (EPI == 2) {
        v += aU[(size_t)m * N + n];
        v = tanhf(v);
        Cb[(size_t)m * N + n] = v;
        O[(((size_t)0 * LL + l) * BB + m) * HH + n] = v;
    } else { // EPI == 3
        O[(size_t)(m + row_off) * N + n] = v;
    }
}

// =======================================================================
// Big GEMM on tensor cores: tf32 mma.sync, 3-stage cp.async pipeline,
// 128x256 block tile, 8 warps of 64x64. Inputs must be pre-rounded tf32.
// Grid: (Mtiles, Ntiles) — M fastest => weight tiles L2-reused per wave.
// =======================================================================
#define CBM 128
#define CBN 256
#define CBK 16
#define NSTG 3
#define ASTR 20                       // row stride in floats (conflict-free)
#define ABUF_FLOATS (CBM * ASTR)      // 2560
#define WBUF_FLOATS (CBN * ASTR)      // 5120
#define SMEM_BYTES (NSTG * (ABUF_FLOATS + WBUF_FLOATS) * 4)   // 92160

__device__ __forceinline__ void cp_async16(uint32_t saddr, const void* gptr, bool ok) {
    int sz = ok ? 16 : 0;
    asm volatile("cp.async.cg.shared.global [%0], [%1], 16, %2;\n"
                 :: "r"(saddr), "l"(gptr), "r"(sz));
}

__device__ __forceinline__ void mma_tf32(float c[4], const unsigned a[4], const unsigned b[2]) {
    asm volatile("mma.sync.aligned.m16n8k8.row.col.f32.tf32.tf32.f32 "
                 "{%0,%1,%2,%3}, {%4,%5,%6,%7}, {%8,%9}, {%0,%1,%2,%3};"
                 : "+f"(c[0]), "+f"(c[1]), "+f"(c[2]), "+f"(c[3])
                 : "r"(a[0]), "r"(a[1]), "r"(a[2]), "r"(a[3]),
                   "r"(b[0]), "r"(b[1]));
}

template <int EPI>
__global__ __launch_bounds__(256, 1)
void tgemm2(int M, int N, int K,
            const float* __restrict__ A,
            const float* __restrict__ W,
            const float* __restrict__ bias,
            const float* __restrict__ aU,
            float* __restrict__ C,
            float* __restrict__ O,
            int t0, int l, int row_off)
{
    extern __shared__ float sm[];

    const int tid  = threadIdx.x;
    const int lane = tid & 31;
    const int wid  = tid >> 5;
    const int wm   = (wid & 1) * 64;     // warp M offset
    const int wn   = (wid >> 1) * 64;    // warp N offset
    const int grp  = lane >> 2;
    const int tig  = lane & 3;

    const int bm = blockIdx.x * CBM;     // M fastest-varying
    const int bn = blockIdx.y * CBN;

    uint32_t sbase;
    asm("{ .reg .u64 t; cvta.to.shared.u64 t, %1; cvt.u32.u64 %0, t; }"
        : "=r"(sbase) : "l"(sm));

    // loader setup: A 2 float4 slots, W 4 float4 slots per thread
    int arow[2], aseg[2];  bool aok[2];  const float* agp[2];  uint32_t asm_[2];
#pragma unroll
    for (int i = 0; i < 2; i++) {
        int slot = tid + 256 * i;
        arow[i] = slot >> 2;
        aseg[i] = (slot & 3) * 4;
        aok[i]  = (bm + arow[i]) < M;
        agp[i]  = A + (size_t)(aok[i] ? bm + arow[i] : 0) * K + aseg[i];
        asm_[i] = sbase + (uint32_t)(arow[i] * ASTR + aseg[i]) * 4;
    }
    int wrow[4], wseg[4];  bool wok[4];  const float* wgp[4];  uint32_t wsm_[4];
#pragma unroll
    for (int i = 0; i < 4; i++) {
        int slot = tid + 256 * i;
        wrow[i] = slot >> 2;
        wseg[i] = (slot & 3) * 4;
        wok[i]  = (bn + wrow[i]) < N;
        wgp[i]  = W + (size_t)(wok[i] ? bn + wrow[i] : 0) * K + wseg[i];
        wsm_[i] = sbase + (uint32_t)(NSTG * ABUF_FLOATS + wrow[i] * ASTR + wseg[i]) * 4;
    }

    float acc[4][8][4];
#pragma unroll
    for (int mf = 0; mf < 4; mf++)
#pragma unroll
        for (int nf = 0; nf < 8; nf++)
#pragma unroll
            for (int r = 0; r < 4; r++) acc[mf][nf][r] = 0.0f;

    const int kT = K / CBK;

    // prologue: stages 0 and 1
#pragma unroll
    for (int s = 0; s < NSTG - 1; s++) {
#pragma unroll
        for (int i = 0; i < 2; i++)
            cp_async16(asm_[i] + s * (ABUF_FLOATS * 4), agp[i] + s * CBK, aok[i]);
#pragma unroll
        for (int i = 0; i < 4; i++)
            cp_async16(wsm_[i] + s * (WBUF_FLOATS * 4), wgp[i] + s * CBK, wok[i]);
        asm volatile("cp.async.commit_group;\n");
    }

    for (int kt = 0; kt < kT; kt++) {
        asm volatile("cp.async.wait_group %0;\n" :: "n"(NSTG - 2));
        __syncthreads();

        // prefetch tile kt + NSTG - 1 (stage buffer was consumed in iter kt-1)
        const int pf = kt + NSTG - 1;
        if (pf < kT) {
            const int ps = pf % NSTG;
#pragma unroll
            for (int i = 0; i < 2; i++)
                cp_async16(asm_[i] + ps * (ABUF_FLOATS * 4), agp[i] + pf * CBK, aok[i]);
#pragma unroll
            for (int i = 0; i < 4; i++)
                cp_async16(wsm_[i] + ps * (WBUF_FLOATS * 4), wgp[i] + pf * CBK, wok[i]);
        }
        asm volatile("cp.async.commit_group;\n");

        const int cb = kt % NSTG;
        const float* Ab = sm + cb * ABUF_FLOATS;
        const float* Wb = sm + NSTG * ABUF_FLOATS + cb * WBUF_FLOATS;

#pragma unroll
        for (int ks = 0; ks < CBK; ks += 8) {
            unsigned af[4][4], bf[8][2];
#pragma unroll
            for (int mf = 0; mf < 4; mf++) {
                int r0 = wm + mf * 16 + grp;
                af[mf][0] = __float_as_uint(Ab[r0 * ASTR + ks + tig]);
                af[mf][1] = __float_as_uint(Ab[(r0 + 8) * ASTR + ks + tig]);
                af[mf][2] = __float_as_uint(Ab[r0 * ASTR + ks + tig + 4]);
                af[mf][3] = __float_as_uint(Ab[(r0 + 8) * ASTR + ks + tig + 4]);
            }
#pragma unroll
            for (int nf = 0; nf < 8; nf++) {
                int c0 = wn + nf * 8 + grp;
                bf[nf][0] = __float_as_uint(Wb[c0 * ASTR + ks + tig]);
                bf[nf][1] = __float_as_uint(Wb[c0 * ASTR + ks + tig + 4]);
            }
#pragma unroll
            for (int mf = 0; mf < 4; mf++)
#pragma unroll
                for (int nf = 0; nf < 8; nf++)
                    mma_tf32(acc[mf][nf], af[mf], bf[nf]);
        }
    }

    // ---- epilogue ----
#pragma unroll
    for (int mf = 0; mf < 4; mf++) {
#pragma unroll
        for (int rh = 0; rh < 2; rh++) {
            int gm = bm + wm + mf * 16 + grp + rh * 8;
            if (gm >= M) continue;
#pragma unroll
            for (int nf = 0; nf < 8; nf++) {
                int gn = bn + wn + nf * 8 + tig * 2;
                if (gn >= N) continue;            // N even → gn+1 ok
                float v0 = acc[mf][nf][rh * 2 + 0] + bias[gn];
                float v1 = acc[mf][nf][rh * 2 + 1] + bias[gn + 1];
                if (EPI == 1) {
                    v0 = tanhf(v0); v1 = tanhf(v1);
                    *reinterpret_cast<float2*>(&C[(size_t)gm * N + gn]) =
                        make_float2(round_tf32f(v0), round_tf32f(v1));
                } else if (EPI == 2) {
                    const float2 au = *reinterpret_cast<const float2*>(
                        &aU[(size_t)(gm & 63) * N + gn]);
                    v0 = tanhf(v0 + au.x);
                    v1 = tanhf(v1 + au.y);
                    *reinterpret_cast<float2*>(&C[(size_t)gm * N + gn]) =
                        make_float2(round_tf32f(v0), round_tf32f(v1));
                    int t = t0 + (gm >> 6);
                    int b = gm & 63;
                    *reinterpret_cast<float2*>(
                        &O[(((size_t)t * LL + l) * BB + b) * HH + gn]) =
                        make_float2(v0, v1);      // h_all output: exact tanh
                } else { // EPI == 3 (logits, exact)
                    *reinterpret_cast<float2*>(&O[(size_t)(gm + row_off) * N + gn]) =
                        make_float2(v0, v1);
                }
            }
        }
    }
}

// ---------------- host-side orchestration -----------------------------------
static inline dim3 tgrid2(int M, int N) {
    return dim3((M + CBM - 1) / CBM, (N + CBN - 1) / CBN);
}

template <int EPI>
static void small_gemm(int N, int K, int nsplit,
                       const float* A, const float* W, const float* bias,
                       const float* aU, float* C, float* O,
                       int l, int row_off, float* part)
{
    dim3 g((N + 63) / 64, nsplit, 1);
    sgemm_splitk<<<g, 256>>>(N, K, A, W, part, 0, 0, 0);
    int total = 64 * N;
    splitk_epi<EPI><<<dim3((total + 255) / 256, 1), 256>>>(
        N, nsplit, part, bias, aU, C, O, l, row_off, 0, 0, 0);
}

// batched pair (z=2) of M=64 GEMMs with EPI 0
static void small_gemm_pair(int N, int K, int nsplit,
                            const float* A, size_t aStr,
                            const float* W, size_t wStr,
                            const float* bias, size_t bStr,
                            float* C, size_t cStr, float* part)
{
    size_t pStr = (size_t)nsplit * 64 * N;
    dim3 g((N + 63) / 64, nsplit, 2);
    sgemm_splitk<<<g, 256>>>(N, K, A, W, part, aStr, wStr, pStr);
    int total = 64 * N;
    splitk_epi<0><<<dim3((total + 255) / 256, 2), 256>>>(
        N, nsplit, part, bias, nullptr, C, nullptr, 0, 0, pStr, bStr, cStr);
}

extern "C" void kernel_launch(void* const* d_in, const int* in_sizes, int n_in,
                              void* d_out, int out_size)
{
    (void)in_sizes; (void)n_in; (void)out_size;
    const int*   inputs = (const int*)  d_in[0];
    const float* hidden = (const float*)d_in[1];   // (L,B,H)
    const float* emb    = (const float*)d_in[2];   // (V,E)
    const float* Ww     = (const float*)d_in[3];   // (L,H,E)
    const float* Wb     = (const float*)d_in[4];   // (L,H)
    const float* Uw     = (const float*)d_in[5];   // (L,H,H)
    const float* Ub     = (const float*)d_in[6];   // (L,H)
    const float* Fw     = (const float*)d_in[7];   // (L,E,H)
    const float* Fb     = (const float*)d_in[8];   // (L,E)
    const float* Dw     = (const float*)d_in[9];   // (V,H)
    const float* Db     = (const float*)d_in[10];  // (V,)

    float* out  = (float*)d_out;
    float* hall = out + (size_t)TT * BB * VV;      // h_all after logits

    float *bufA, *bufB, *x0, *xt, *xt2, *h0, *aU, *part;
    float *WwR, *FwR, *DwR;
    cudaGetSymbolAddress((void**)&bufA, g_bufA);
    cudaGetSymbolAddress((void**)&bufB, g_bufB);
    cudaGetSymbolAddress((void**)&x0,  g_x0);
    cudaGetSymbolAddress((void**)&xt,  g_xt);
    cudaGetSymbolAddress((void**)&xt2, g_xt2);
    cudaGetSymbolAddress((void**)&h0,  g_h0);
    cudaGetSymbolAddress((void**)&aU,  g_aU);
    cudaGetSymbolAddress((void**)&part, g_part);
    cudaGetSymbolAddress((void**)&WwR, g_WwR);
    cudaGetSymbolAddress((void**)&FwR, g_FwR);
    cudaGetSymbolAddress((void**)&DwR, g_DwR);

    float* h00 = h0;
    float* h01 = h0 + (size_t)BB * HH;
    float* aU0 = aU;
    float* aU1 = aU + (size_t)BB * HH;

    cudaFuncSetAttribute(tgemm2<1>, cudaFuncAttributeMaxDynamicSharedMemorySize, SMEM_BYTES);
    cudaFuncSetAttribute(tgemm2<2>, cudaFuncAttributeMaxDynamicSharedMemorySize, SMEM_BYTES);
    cudaFuncSetAttribute(tgemm2<3>, cudaFuncAttributeMaxDynamicSharedMemorySize, SMEM_BYTES);

    const size_t Wstride = (size_t)HH * EE;

    // ---- pre-round weights to tf32 ----
    {
        int n4;
        n4 = (LL * HH * EE) / 4;
        round_tf32_kernel<<<(n4 + 255) / 256, 256>>>(Ww, WwR, n4);
        n4 = (LL * EE * HH) / 4;
        round_tf32_kernel<<<(n4 + 255) / 256, 256>>>(Fw, FwR, n4);
        n4 = (VV * HH) / 4;
        round_tf32_kernel<<<(n4 + 255) / 256, 256>>>(Dw, DwR, n4);
    }

    // ---- Phase A: t = 0 (sequential small GEMMs, M = 64, split-K fp32) ----
    gather_emb<<<(BB * 256 + 255) / 256, 256>>>(inputs, emb, x0, 0, BB, 0);

    // aU pair from initial hidden (both layers at once)
    small_gemm_pair(HH, HH, 16, hidden, (size_t)BB * HH, Uw, Wstride,
                    Ub, HH, aU, (size_t)BB * HH, part);
    small_gemm<2>(HH, EE, 16, x0, Ww, Wb, aU0, h00, hall, 0, 0, part);
    small_gemm<1>(EE, HH, 16, h00, Fw, Fb, nullptr, xt, nullptr, 0, 0, part);
    small_gemm<2>(HH, EE, 16, xt, Ww + Wstride, Wb + HH, aU1, h01, hall, 1, 0, part);
    small_gemm<1>(EE, HH, 16, h01, Fw + Wstride, Fb + EE, nullptr, xt2, nullptr, 0, 0, part);
    small_gemm<3>(VV, HH, 4, xt2, Dw, Db, nullptr, nullptr, out, 0, 0, part);

    // ---- fixed recurrent terms for t >= 1 (pair, from h00/h01) ----
    small_gemm_pair(HH, HH, 16, h0, (size_t)BB * HH, Uw, Wstride,
                    Ub, HH, aU, (size_t)BB * HH, part);

    // ---- Phase B: t = 1..127 batched (M = 8128) on tensor cores ----
    gather_emb<<<(MREST * 256 + 255) / 256, 256>>>(inputs, emb, bufA, BB, MREST, 1);

    tgemm2<2><<<tgrid2(MREST, HH), 256, SMEM_BYTES>>>(MREST, HH, EE, bufA, WwR, Wb,
                                                      aU0, bufB, hall, 1, 0, 0);
    tgemm2<1><<<tgrid2(MREST, EE), 256, SMEM_BYTES>>>(MREST, EE, HH, bufB, FwR, Fb,
                                                      nullptr, bufA, nullptr, 0, 0, 0);
    tgemm2<2><<<tgrid2(MREST, HH), 256, SMEM_BYTES>>>(MREST, HH, EE, bufA,
                                                      WwR + Wstride, Wb + HH,
                                                      aU1, bufB, hall, 1, 1, 0);
    tgemm2<1><<<tgrid2(MREST, EE), 256, SMEM_BYTES>>>(MREST, EE, HH, bufB,
                                                      FwR + Wstride, Fb + EE,
                                                      nullptr, bufA, nullptr, 0, 0, 0);
    tgemm2<3><<<tgrid2(MREST, VV), 256, SMEM_BYTES>>>(MREST, VV, HH, bufA, DwR, Db,
                                                      nullptr, nullptr, out, 0, 0, BB);
}